// round 10
// baseline (speedup 1.0000x reference)
#include <cuda_runtime.h>
#include <cuda_fp16.h>

// ---------------------------------------------------------------------------
// MutationAwareGNN R10: stride-32 layers (layer-1 pre-agg, layer-3) moved to
// fp32 — removes all cvt arithmetic from those aggs (4 FADDs per uint4 instead
// of 8 cvt + 8 add) and shrinks the shfl reduction. Layer-2 agg stays fp16
// (256B fp32 rows would be L2-bound). Padded buckets (mult of 8) + zero-row
// sentinels, guard-free agg loops, 8-edge/thread fill.
// ---------------------------------------------------------------------------

#define NMAX 100000
#define EMAX 3200000
#define GMAX 256
#define CAP  128          // bucket capacity (Poisson(32) degrees: safe)

__device__ int    g_cnt[NMAX];
__device__ int    g_cnte8[NMAX];             // padded count, multiple of 8
__device__ int    g_col[(NMAX + 1) * CAP];   // +1 spare bucket absorbs over-reads
__device__ float  g_dinv[NMAX];
__device__ float  g_f0[(NMAX + 1) * 32];     // fp32 stride-32 (prep out / gemm3 out)
__device__ float  g_f1[(NMAX + 1) * 32];     // fp32 stride-32 (agg1 out / agg3 out)
__device__ __half g_hA[(NMAX + 1) * 64];     // fp16 stride-64 (gemm1 out / agg2 out)
__device__ __half g_hB[(NMAX + 1) * 64];     // fp16 stride-64 (gemm2 out)

// ---------------------------- Bucket fill ----------------------------------

__global__ void k_fill(const int* __restrict__ src, const int* __restrict__ dst, int E) {
    int e8 = (blockIdx.x * blockDim.x + threadIdx.x) * 8;
    if (e8 + 7 < E) {
        int4 s0 = *reinterpret_cast<const int4*>(&src[e8]);
        int4 s1 = *reinterpret_cast<const int4*>(&src[e8 + 4]);
        int4 d0 = *reinterpret_cast<const int4*>(&dst[e8]);
        int4 d1 = *reinterpret_cast<const int4*>(&dst[e8 + 4]);
        int p0 = atomicAdd(&g_cnt[d0.x], 1);
        int p1 = atomicAdd(&g_cnt[d0.y], 1);
        int p2 = atomicAdd(&g_cnt[d0.z], 1);
        int p3 = atomicAdd(&g_cnt[d0.w], 1);
        int p4 = atomicAdd(&g_cnt[d1.x], 1);
        int p5 = atomicAdd(&g_cnt[d1.y], 1);
        int p6 = atomicAdd(&g_cnt[d1.z], 1);
        int p7 = atomicAdd(&g_cnt[d1.w], 1);
        if (p0 < CAP) g_col[d0.x * CAP + p0] = s0.x;
        if (p1 < CAP) g_col[d0.y * CAP + p1] = s0.y;
        if (p2 < CAP) g_col[d0.z * CAP + p2] = s0.z;
        if (p3 < CAP) g_col[d0.w * CAP + p3] = s0.w;
        if (p4 < CAP) g_col[d1.x * CAP + p4] = s1.x;
        if (p5 < CAP) g_col[d1.y * CAP + p5] = s1.y;
        if (p6 < CAP) g_col[d1.z * CAP + p6] = s1.z;
        if (p7 < CAP) g_col[d1.w * CAP + p7] = s1.w;
    } else {
        for (int e = e8; e < E; e++) {
            int d = dst[e];
            int p = atomicAdd(&g_cnt[d], 1);
            if (p < CAP) g_col[d * CAP + p] = src[e];
        }
    }
}

// dinv + pad buckets to multiple of 8 with sentinel index n (zero row).
__global__ void k_dinv_pad(int n) {
    int i = blockIdx.x * blockDim.x + threadIdx.x;
    if (i >= n) return;
    int c   = min(g_cnt[i], CAP);
    int ce8 = (c + 7) & ~7;
    for (int s = c; s < ce8; s++) g_col[i * CAP + s] = n;  // sentinel -> zero row
    g_cnte8[i] = ce8;
    g_dinv[i]  = rsqrtf((float)(c + 1));                   // +1 self-loop
}

// ------------------------------ Prep (layer 1) ------------------------------
// g_f0 rows 0..n-1 = dinv_j * x_j (25 features padded to 32 fp32); row n = 0.

__global__ void k_prep(const float* __restrict__ x, int n) {
    int i = blockIdx.x * blockDim.x + threadIdx.x;   // float4 slot
    if (i >= (n + 1) * 8) return;
    int node = i >> 3, f4 = i & 7;
    float4 v = make_float4(0.f, 0.f, 0.f, 0.f);
    if (node < n) {
        float d = g_dinv[node];
        int f = f4 * 4;
        if (f     < 25) v.x = d * __ldg(&x[node * 25 + f]);
        if (f + 1 < 25) v.y = d * __ldg(&x[node * 25 + f + 1]);
        if (f + 2 < 25) v.z = d * __ldg(&x[node * 25 + f + 2]);
        if (f + 3 < 25) v.w = d * __ldg(&x[node * 25 + f + 3]);
    }
    reinterpret_cast<float4*>(g_f0)[i] = v;
}

// ----------------------- Aggregation, fp32 stride-32 ------------------------
// Warp per node: 8 lanes x float4 cover a 32-float row; 4 edge groups,
// 2-unrolled, guard-free (buckets padded to mult 8, sentinel row n = 0).
// Reads g_f0, writes g_f1. RELU=1 adds bias + relu; RELU=0 scales only.

template <int RELU>
__global__ void k_agg_f32(const float* __restrict__ bias, int n) {
    int gw   = (blockIdx.x * blockDim.x + threadIdx.x) >> 5;
    int lane = threadIdx.x & 31;
    if (gw >= n) return;
    int grp = lane >> 3;          // 0..3 edge groups
    int sub = lane & 7;           // float4 chunk within row
    int beg  = gw * CAP;
    int endv = beg + g_cnte8[gw];

    const float4* base = reinterpret_cast<const float4*>(g_f0);

    float4 acc = make_float4(0.f, 0.f, 0.f, 0.f);
    if (grp == 0) acc = base[gw * 8 + sub];     // self-loop term

    int e  = beg + grp;
    int j0 = __ldg(&g_col[e]);
    int j1 = __ldg(&g_col[e + 4]);
    while (e < endv) {
        float4 v0 = base[j0 * 8 + sub];
        float4 v1 = base[j1 * 8 + sub];
        e += 8;
        j0 = __ldg(&g_col[e]);    // unconditional (spare bucket absorbs)
        j1 = __ldg(&g_col[e + 4]);
        acc.x += v0.x + v1.x;
        acc.y += v0.y + v1.y;
        acc.z += v0.z + v1.z;
        acc.w += v0.w + v1.w;
    }

#pragma unroll
    for (int off = 8; off < 32; off <<= 1) {
        acc.x += __shfl_xor_sync(0xffffffffu, acc.x, off);
        acc.y += __shfl_xor_sync(0xffffffffu, acc.y, off);
        acc.z += __shfl_xor_sync(0xffffffffu, acc.z, off);
        acc.w += __shfl_xor_sync(0xffffffffu, acc.w, off);
    }

    if (grp == 0) {
        float d = g_dinv[gw];
        float4 r;
        if (RELU) {
            float4 b = __ldg(reinterpret_cast<const float4*>(&bias[sub * 4]));
            r.x = fmaxf(fmaf(acc.x, d, b.x), 0.f);
            r.y = fmaxf(fmaf(acc.y, d, b.y), 0.f);
            r.z = fmaxf(fmaf(acc.z, d, b.z), 0.f);
            r.w = fmaxf(fmaf(acc.w, d, b.w), 0.f);
        } else {
            r.x = acc.x * d; r.y = acc.y * d; r.z = acc.z * d; r.w = acc.w * d;
        }
        reinterpret_cast<float4*>(g_f1)[gw * 8 + sub] = r;
    }
}

// ----------------------- Aggregation, fp16 stride-64 (layer 2) --------------
// Reads g_hB, writes g_hA. relu(dinv*acc + bias). 8 lanes x uint4 per row.

__global__ void k_agg_h64(const float* __restrict__ bias, int n) {
    int gw   = (blockIdx.x * blockDim.x + threadIdx.x) >> 5;
    int lane = threadIdx.x & 31;
    if (gw >= n) return;
    int grp = lane >> 3;
    int sub = lane & 7;
    int beg  = gw * CAP;
    int endv = beg + g_cnte8[gw];

    const uint4* base = reinterpret_cast<const uint4*>(g_hB);

    float acc[8] = {0.f, 0.f, 0.f, 0.f, 0.f, 0.f, 0.f, 0.f};
    auto accum = [&](uint4 v) {
        float2 f0 = __half22float2(*reinterpret_cast<__half2*>(&v.x));
        float2 f1 = __half22float2(*reinterpret_cast<__half2*>(&v.y));
        float2 f2 = __half22float2(*reinterpret_cast<__half2*>(&v.z));
        float2 f3 = __half22float2(*reinterpret_cast<__half2*>(&v.w));
        acc[0] += f0.x; acc[1] += f0.y; acc[2] += f1.x; acc[3] += f1.y;
        acc[4] += f2.x; acc[5] += f2.y; acc[6] += f3.x; acc[7] += f3.y;
    };
    if (grp == 0) accum(base[gw * 8 + sub]);   // self-loop

    int e  = beg + grp;
    int j0 = __ldg(&g_col[e]);
    int j1 = __ldg(&g_col[e + 4]);
    while (e < endv) {
        uint4 v0 = base[j0 * 8 + sub];
        uint4 v1 = base[j1 * 8 + sub];
        e += 8;
        j0 = __ldg(&g_col[e]);
        j1 = __ldg(&g_col[e + 4]);
        accum(v0);
        accum(v1);
    }

#pragma unroll
    for (int off = 8; off < 32; off <<= 1) {
#pragma unroll
        for (int k = 0; k < 8; k++)
            acc[k] += __shfl_xor_sync(0xffffffffu, acc[k], off);
    }

    if (grp == 0) {
        float d = g_dinv[gw];
        __half out[8];
#pragma unroll
        for (int k = 0; k < 8; k++)
            out[k] = __float2half_rn(fmaxf(fmaf(acc[k], d, __ldg(&bias[sub * 8 + k])), 0.f));
        reinterpret_cast<uint4*>(g_hA)[gw * 8 + sub] = *reinterpret_cast<uint4*>(out);
    }
}

// --------------------------- GEMM 1: fp32 -> fp16 ---------------------------
// g_f1[n,32] @ W1[25x64 padded 32] + b1, relu -> g_hA (stride 64). 2 rows/thr.

__global__ void k_gemm1(const float* __restrict__ W, const float* __restrict__ bias, int n) {
    __shared__ float Wsh[32 * 64];
    for (int i = threadIdx.x; i < 32 * 64; i += blockDim.x)
        Wsh[i] = (i < 25 * 64) ? W[i] : 0.f;
    __syncthreads();

    int slot = (int)(threadIdx.x >> 4);          // TPR=16
    int row0 = blockIdx.x * 32 + slot;
    int row1 = row0 + 16;
    int fx = (threadIdx.x & 15) * 4;
    bool v1 = row1 < n;
    if (row0 >= n) return;

    const float4* xr0 = reinterpret_cast<const float4*>(g_f1 + (long)row0 * 32);
    const float4* xr1 = reinterpret_cast<const float4*>(g_f1 + (long)(v1 ? row1 : row0) * 32);
    float4 a0 = make_float4(0.f, 0.f, 0.f, 0.f);
    float4 a1 = make_float4(0.f, 0.f, 0.f, 0.f);
#pragma unroll
    for (int q = 0; q < 8; q++) {
        float4 p0 = __ldg(&xr0[q]);
        float4 p1 = __ldg(&xr1[q]);
        const float* c0 = &p0.x;
        const float* c1 = &p1.x;
#pragma unroll
        for (int t = 0; t < 4; t++) {
            int k = q * 4 + t;
            float4 w = *reinterpret_cast<const float4*>(&Wsh[k * 64 + fx]);
            a0.x = fmaf(c0[t], w.x, a0.x); a0.y = fmaf(c0[t], w.y, a0.y);
            a0.z = fmaf(c0[t], w.z, a0.z); a0.w = fmaf(c0[t], w.w, a0.w);
            a1.x = fmaf(c1[t], w.x, a1.x); a1.y = fmaf(c1[t], w.y, a1.y);
            a1.z = fmaf(c1[t], w.z, a1.z); a1.w = fmaf(c1[t], w.w, a1.w);
        }
    }
    float4 b = __ldg(reinterpret_cast<const float4*>(&bias[fx]));
    {
        __half2* op = reinterpret_cast<__half2*>(&g_hA[(long)row0 * 64 + fx]);
        op[0] = __floats2half2_rn(fmaxf(a0.x + b.x, 0.f), fmaxf(a0.y + b.y, 0.f));
        op[1] = __floats2half2_rn(fmaxf(a0.z + b.z, 0.f), fmaxf(a0.w + b.w, 0.f));
    }
    if (v1) {
        __half2* op = reinterpret_cast<__half2*>(&g_hA[(long)row1 * 64 + fx]);
        op[0] = __floats2half2_rn(fmaxf(a1.x + b.x, 0.f), fmaxf(a1.y + b.y, 0.f));
        op[1] = __floats2half2_rn(fmaxf(a1.z + b.z, 0.f), fmaxf(a1.w + b.w, 0.f));
    }
}

// --------------------------- GEMM 2: fp16 -> fp16 ---------------------------
// g_hA[n,64] @ W2[64x64], scaled by dinv_row -> g_hB. Writes zero sentinel.

__global__ void k_gemm2(const float* __restrict__ W, int n) {
    __shared__ float Wsh[64 * 64];
    for (int i = threadIdx.x; i < 64 * 64; i += blockDim.x) Wsh[i] = W[i];
    __syncthreads();

    if (blockIdx.x == 0 && threadIdx.x < 8) {    // zero sentinel row n (128B)
        reinterpret_cast<uint4*>(g_hB)[(long)n * 8 + threadIdx.x] =
            make_uint4(0u, 0u, 0u, 0u);
    }

    int slot = (int)(threadIdx.x >> 4);          // TPR=16
    int row0 = blockIdx.x * 32 + slot;
    int row1 = row0 + 16;
    int fx = (threadIdx.x & 15) * 4;
    bool v1 = row1 < n;
    if (row0 >= n) return;

    const uint4* xr0 = reinterpret_cast<const uint4*>(g_hA + (long)row0 * 64);
    const uint4* xr1 = reinterpret_cast<const uint4*>(g_hA + (long)(v1 ? row1 : row0) * 64);
    float4 a0 = make_float4(0.f, 0.f, 0.f, 0.f);
    float4 a1 = make_float4(0.f, 0.f, 0.f, 0.f);
#pragma unroll
    for (int q = 0; q < 8; q++) {
        uint4 p0 = __ldg(&xr0[q]);
        uint4 p1 = __ldg(&xr1[q]);
        const unsigned* u0 = &p0.x;
        const unsigned* u1 = &p1.x;
#pragma unroll
        for (int t = 0; t < 4; t++) {
            float2 f0 = __half22float2(*reinterpret_cast<const __half2*>(&u0[t]));
            float2 f1 = __half22float2(*reinterpret_cast<const __half2*>(&u1[t]));
            int k = q * 8 + t * 2;
            float4 w0 = *reinterpret_cast<const float4*>(&Wsh[k * 64 + fx]);
            float4 w1 = *reinterpret_cast<const float4*>(&Wsh[(k + 1) * 64 + fx]);
            a0.x = fmaf(f0.x, w0.x, fmaf(f0.y, w1.x, a0.x));
            a0.y = fmaf(f0.x, w0.y, fmaf(f0.y, w1.y, a0.y));
            a0.z = fmaf(f0.x, w0.z, fmaf(f0.y, w1.z, a0.z));
            a0.w = fmaf(f0.x, w0.w, fmaf(f0.y, w1.w, a0.w));
            a1.x = fmaf(f1.x, w0.x, fmaf(f1.y, w1.x, a1.x));
            a1.y = fmaf(f1.x, w0.y, fmaf(f1.y, w1.y, a1.y));
            a1.z = fmaf(f1.x, w0.z, fmaf(f1.y, w1.z, a1.z));
            a1.w = fmaf(f1.x, w0.w, fmaf(f1.y, w1.w, a1.w));
        }
    }
    {
        float d = g_dinv[row0];
        __half2* op = reinterpret_cast<__half2*>(&g_hB[(long)row0 * 64 + fx]);
        op[0] = __floats2half2_rn(a0.x * d, a0.y * d);
        op[1] = __floats2half2_rn(a0.z * d, a0.w * d);
    }
    if (v1) {
        float d = g_dinv[row1];
        __half2* op = reinterpret_cast<__half2*>(&g_hB[(long)row1 * 64 + fx]);
        op[0] = __floats2half2_rn(a1.x * d, a1.y * d);
        op[1] = __floats2half2_rn(a1.z * d, a1.w * d);
    }
}

// --------------------------- GEMM 3: fp16 -> fp32 ---------------------------
// g_hA[n,64] @ W3[64x32], scaled by dinv_row -> g_f0 (stride 32). Sentinel.

__global__ void k_gemm3(const float* __restrict__ W, int n) {
    __shared__ float Wsh[64 * 32];
    for (int i = threadIdx.x; i < 64 * 32; i += blockDim.x) Wsh[i] = W[i];
    __syncthreads();

    if (blockIdx.x == 0 && threadIdx.x < 8) {    // zero sentinel row n (128B)
        reinterpret_cast<float4*>(g_f0)[(long)n * 8 + threadIdx.x] =
            make_float4(0.f, 0.f, 0.f, 0.f);
    }

    int slot = (int)(threadIdx.x >> 3);          // TPR=8
    int row0 = blockIdx.x * 64 + slot;
    int row1 = row0 + 32;
    int fx = (threadIdx.x & 7) * 4;
    bool v1 = row1 < n;
    if (row0 >= n) return;

    const uint4* xr0 = reinterpret_cast<const uint4*>(g_hA + (long)row0 * 64);
    const uint4* xr1 = reinterpret_cast<const uint4*>(g_hA + (long)(v1 ? row1 : row0) * 64);
    float4 a0 = make_float4(0.f, 0.f, 0.f, 0.f);
    float4 a1 = make_float4(0.f, 0.f, 0.f, 0.f);
#pragma unroll
    for (int q = 0; q < 8; q++) {
        uint4 p0 = __ldg(&xr0[q]);
        uint4 p1 = __ldg(&xr1[q]);
        const unsigned* u0 = &p0.x;
        const unsigned* u1 = &p1.x;
#pragma unroll
        for (int t = 0; t < 4; t++) {
            float2 f0 = __half22float2(*reinterpret_cast<const __half2*>(&u0[t]));
            float2 f1 = __half22float2(*reinterpret_cast<const __half2*>(&u1[t]));
            int k = q * 8 + t * 2;
            float4 w0 = *reinterpret_cast<const float4*>(&Wsh[k * 32 + fx]);
            float4 w1 = *reinterpret_cast<const float4*>(&Wsh[(k + 1) * 32 + fx]);
            a0.x = fmaf(f0.x, w0.x, fmaf(f0.y, w1.x, a0.x));
            a0.y = fmaf(f0.x, w0.y, fmaf(f0.y, w1.y, a0.y));
            a0.z = fmaf(f0.x, w0.z, fmaf(f0.y, w1.z, a0.z));
            a0.w = fmaf(f0.x, w0.w, fmaf(f0.y, w1.w, a0.w));
            a1.x = fmaf(f1.x, w0.x, fmaf(f1.y, w1.x, a1.x));
            a1.y = fmaf(f1.x, w0.y, fmaf(f1.y, w1.y, a1.y));
            a1.z = fmaf(f1.x, w0.z, fmaf(f1.y, w1.z, a1.z));
            a1.w = fmaf(f1.x, w0.w, fmaf(f1.y, w1.w, a1.w));
        }
    }
    {
        float d = g_dinv[row0];
        *reinterpret_cast<float4*>(&g_f0[(long)row0 * 32 + fx]) =
            make_float4(a0.x * d, a0.y * d, a0.z * d, a0.w * d);
    }
    if (v1) {
        float d = g_dinv[row1];
        *reinterpret_cast<float4*>(&g_f0[(long)row1 * 32 + fx]) =
            make_float4(a1.x * d, a1.y * d, a1.z * d, a1.w * d);
    }
}

// ------------------------- Pool + MLP head (fused) --------------------------
// Final features fp32 in g_f1 (stride 32).

__global__ void k_pool_mlp(const int* __restrict__ batch, int n,
                           const float* __restrict__ Wh1, const float* __restrict__ bh1,
                           const float* __restrict__ Wh2, const float* __restrict__ bh2,
                           float* __restrict__ out) {
    int g = blockIdx.x;
    int lo = 0, hi = n;
    while (lo < hi) { int mid = (lo + hi) >> 1; if (batch[mid] < g) lo = mid + 1; else hi = mid; }
    int start = lo;
    hi = n;
    while (lo < hi) { int mid = (lo + hi) >> 1; if (batch[mid] < g + 1) lo = mid + 1; else hi = mid; }
    int end = lo;

    __shared__ float partial[4][32];
    __shared__ float gsum[32];
    int f = threadIdx.x & 31;
    int r = threadIdx.x >> 5;
    float acc = 0.f;
    for (int i = start + r; i < end; i += 4) acc += g_f1[(long)i * 32 + f];
    partial[r][f] = acc;
    __syncthreads();

    if (threadIdx.x < 32) {
        float s = partial[0][f] + partial[1][f] + partial[2][f] + partial[3][f];
        float cnt = (float)((end - start) > 0 ? (end - start) : 1);
        gsum[f] = s / cnt;
    }
    __syncthreads();

    if (threadIdx.x < 32) {
        int o = threadIdx.x;
        float h = bh1[o];
#pragma unroll
        for (int k = 0; k < 32; k++) h = fmaf(gsum[k], Wh1[k * 32 + o], h);
        h = fmaxf(h, 0.f);
        float y = h * Wh2[o];
#pragma unroll
        for (int off = 16; off; off >>= 1) y += __shfl_down_sync(0xffffffffu, y, off);
        if (o == 0) out[g] = y + bh2[0];
    }
}

// ------------------------------- Launcher ----------------------------------

extern "C" void kernel_launch(void* const* d_in, const int* in_sizes, int n_in,
                              void* d_out, int out_size) {
    const float* x     = (const float*)d_in[0];
    const int*   ei    = (const int*)d_in[1];
    const int*   batch = (const int*)d_in[2];
    const float* W1  = (const float*)d_in[3];
    const float* b1  = (const float*)d_in[4];
    const float* W2  = (const float*)d_in[5];
    const float* b2  = (const float*)d_in[6];
    const float* W3  = (const float*)d_in[7];
    const float* b3  = (const float*)d_in[8];
    const float* Wh1 = (const float*)d_in[9];
    const float* bh1 = (const float*)d_in[10];
    const float* Wh2 = (const float*)d_in[11];
    const float* bh2 = (const float*)d_in[12];
    float* out = (float*)d_out;

    int N = in_sizes[0] / 25;
    int E = in_sizes[1] / 2;
    const int* src = ei;
    const int* dst = ei + E;

    int nThreads = 256;
    int nBlkN = (N + nThreads - 1) / nThreads;
    int nBlkE8 = (E + nThreads * 8 - 1) / (nThreads * 8);
    int aggBlocks = (N + 7) / 8;

    // --- Clear counters ---
    void* p = nullptr;
    cudaGetSymbolAddress(&p, g_cnt);
    cudaMemsetAsync(p, 0, N * sizeof(int));

    // --- Bucket adjacency build (single edge pass) ---
    k_fill<<<nBlkE8, nThreads>>>(src, dst, E);
    k_dinv_pad<<<nBlkN, nThreads>>>(N);

    // --- Layer 1: prep (fp32) -> aggregate -> 25->64 GEMM ---
    k_prep<<<((N + 1) * 8 + 255) / 256, 256>>>(x, N);        // x -> f0 (+sentinel)
    k_agg_f32<0><<<aggBlocks, 256>>>(nullptr, N);            // f0 -> f1
    k_gemm1<<<(N + 31) / 32, 256>>>(W1, b1, N);              // f1 -> hA

    // --- Layer 2 (fp16) ---
    k_gemm2<<<(N + 31) / 32, 256>>>(W2, N);                  // hA -> hB (+sentinel)
    k_agg_h64<<<aggBlocks, 256>>>(b2, N);                    // hB -> hA

    // --- Layer 3 (fp32 out) ---
    k_gemm3<<<(N + 63) / 64, 256>>>(W3, N);                  // hA -> f0 (+sentinel)
    k_agg_f32<1><<<aggBlocks, 256>>>(b3, N);                 // f0 -> f1

    // --- Pool + MLP head ---
    k_pool_mlp<<<GMAX, 128>>>(batch, N, Wh1, bh1, Wh2, bh2, out);
}

// round 11
// speedup vs baseline: 1.1521x; 1.1521x over previous
#include <cuda_runtime.h>
#include <cuda_fp16.h>

// ---------------------------------------------------------------------------
// MutationAwareGNN R11: node-per-lane-group aggregation — each group of
// F/8 lanes owns ONE node and walks its whole bucket (no shfl reduction,
// no group-0 divergence, trip count ~deg/2). Pairwise HADD2 pre-add halves
// conversion arithmetic. Buckets padded to multiple of 2 only. fp16 storage,
// fp32 accumulate, bucket adjacency, zero-row sentinels (R9 scheme).
// ---------------------------------------------------------------------------

#define NMAX 100000
#define EMAX 3200000
#define GMAX 256
#define CAP  128          // bucket capacity (Poisson(32) degrees: safe)

__device__ int    g_cnt[NMAX];
__device__ int    g_cnte2[NMAX];             // padded count, multiple of 2
__device__ int    g_col[(NMAX + 1) * CAP];   // +1 spare bucket absorbs over-reads
__device__ float  g_dinv[NMAX];
__device__ __half g_hA[(NMAX + 1) * 64];     // row n = zero sentinel (per layout)
__device__ __half g_hB[(NMAX + 1) * 64];

// ---------------------------- Bucket fill ----------------------------------

__global__ void k_fill(const int* __restrict__ src, const int* __restrict__ dst, int E) {
    int e8 = (blockIdx.x * blockDim.x + threadIdx.x) * 8;
    if (e8 + 7 < E) {
        int4 s0 = *reinterpret_cast<const int4*>(&src[e8]);
        int4 s1 = *reinterpret_cast<const int4*>(&src[e8 + 4]);
        int4 d0 = *reinterpret_cast<const int4*>(&dst[e8]);
        int4 d1 = *reinterpret_cast<const int4*>(&dst[e8 + 4]);
        int p0 = atomicAdd(&g_cnt[d0.x], 1);
        int p1 = atomicAdd(&g_cnt[d0.y], 1);
        int p2 = atomicAdd(&g_cnt[d0.z], 1);
        int p3 = atomicAdd(&g_cnt[d0.w], 1);
        int p4 = atomicAdd(&g_cnt[d1.x], 1);
        int p5 = atomicAdd(&g_cnt[d1.y], 1);
        int p6 = atomicAdd(&g_cnt[d1.z], 1);
        int p7 = atomicAdd(&g_cnt[d1.w], 1);
        if (p0 < CAP) g_col[d0.x * CAP + p0] = s0.x;
        if (p1 < CAP) g_col[d0.y * CAP + p1] = s0.y;
        if (p2 < CAP) g_col[d0.z * CAP + p2] = s0.z;
        if (p3 < CAP) g_col[d0.w * CAP + p3] = s0.w;
        if (p4 < CAP) g_col[d1.x * CAP + p4] = s1.x;
        if (p5 < CAP) g_col[d1.y * CAP + p5] = s1.y;
        if (p6 < CAP) g_col[d1.z * CAP + p6] = s1.z;
        if (p7 < CAP) g_col[d1.w * CAP + p7] = s1.w;
    } else {
        for (int e = e8; e < E; e++) {
            int d = dst[e];
            int p = atomicAdd(&g_cnt[d], 1);
            if (p < CAP) g_col[d * CAP + p] = src[e];
        }
    }
}

// dinv + pad buckets to multiple of 2 with sentinel index n (zero row).
__global__ void k_dinv_pad(int n) {
    int i = blockIdx.x * blockDim.x + threadIdx.x;
    if (i >= n) return;
    int c   = min(g_cnt[i], CAP);
    int ce2 = (c + 1) & ~1;
    if (c & 1) g_col[i * CAP + c] = n;   // sentinel -> zero row
    g_cnte2[i] = ce2;
    g_dinv[i]  = rsqrtf((float)(c + 1)); // +1 self-loop
}

// ------------------------------ Prep (layer 1) ------------------------------
// g_hA rows 0..n-1 = dinv_j * x_j (25 features padded to 32 fp16); row n = 0.

__global__ void k_prep(const float* __restrict__ x, int n) {
    int i = blockIdx.x * blockDim.x + threadIdx.x;   // half2 slot
    if (i >= (n + 1) * 16) return;
    int node = i >> 4, f2 = i & 15;
    float a = 0.f, b = 0.f;
    if (node < n) {
        float d = g_dinv[node];
        int f = f2 * 2;
        a = (f     < 25) ? d * __ldg(&x[node * 25 + f])     : 0.f;
        b = (f + 1 < 25) ? d * __ldg(&x[node * 25 + f + 1]) : 0.f;
    }
    reinterpret_cast<__half2*>(g_hA)[i] = __floats2half2_rn(a, b);
}

// ----------------------------- Aggregation ---------------------------------
// Node-per-lane-group: U4R = F/8 lanes cover one row (uint4 each); a warp
// owns GPN = 32/U4R nodes. Each group walks its node's bucket, 2 edges per
// iteration (pairwise HADD2, then fp32 accumulate). No cross-lane reduction.
// Guard-free loop: buckets padded to multiple of 2, sentinel row n is zero.

template <int F, int RELU, int SRC>
__global__ void k_agg_g(const float* __restrict__ bias, int n) {
    constexpr int U4R = F / 8;        // lanes per row: 8 (F=64) or 4 (F=32)
    constexpr int GPN = 32 / U4R;     // nodes per warp: 4 or 8
    int wid  = (blockIdx.x * blockDim.x + threadIdx.x) >> 5;
    int lane = threadIdx.x & 31;
    int grp = lane / U4R;
    int sub = lane % U4R;
    int node = wid * GPN + grp;
    bool valid = node < n;
    int nd = valid ? node : n;        // sentinel row is safe to gather

    const uint4* base = reinterpret_cast<const uint4*>(SRC ? g_hB : g_hA);
    __half*      db   = SRC ? g_hA : g_hB;

    // self-loop term
    float acc[8];
    {
        uint4 v = base[nd * U4R + sub];
        float2 f0 = __half22float2(*reinterpret_cast<__half2*>(&v.x));
        float2 f1 = __half22float2(*reinterpret_cast<__half2*>(&v.y));
        float2 f2 = __half22float2(*reinterpret_cast<__half2*>(&v.z));
        float2 f3 = __half22float2(*reinterpret_cast<__half2*>(&v.w));
        acc[0] = f0.x; acc[1] = f0.y; acc[2] = f1.x; acc[3] = f1.y;
        acc[4] = f2.x; acc[5] = f2.y; acc[6] = f3.x; acc[7] = f3.y;
    }

    int e    = node * CAP;            // int: max ~12.8M, fits
    int endv = e + (valid ? g_cnte2[node] : 0);
    int2 jj = *reinterpret_cast<const int2*>(&g_col[e]);   // broadcast in group
    while (e < endv) {
        uint4 v0 = base[jj.x * U4R + sub];
        uint4 v1 = base[jj.y * U4R + sub];
        e += 2;
        jj = *reinterpret_cast<const int2*>(&g_col[e]);    // prefetch (unused at exit)
        // pairwise fp16 add, then fp32 accumulate
        __half2 s0 = __hadd2(*reinterpret_cast<__half2*>(&v0.x), *reinterpret_cast<__half2*>(&v1.x));
        __half2 s1 = __hadd2(*reinterpret_cast<__half2*>(&v0.y), *reinterpret_cast<__half2*>(&v1.y));
        __half2 s2 = __hadd2(*reinterpret_cast<__half2*>(&v0.z), *reinterpret_cast<__half2*>(&v1.z));
        __half2 s3 = __hadd2(*reinterpret_cast<__half2*>(&v0.w), *reinterpret_cast<__half2*>(&v1.w));
        float2 f0 = __half22float2(s0);
        float2 f1 = __half22float2(s1);
        float2 f2 = __half22float2(s2);
        float2 f3 = __half22float2(s3);
        acc[0] += f0.x; acc[1] += f0.y; acc[2] += f1.x; acc[3] += f1.y;
        acc[4] += f2.x; acc[5] += f2.y; acc[6] += f3.x; acc[7] += f3.y;
    }

    if (valid) {
        float d = g_dinv[node];
        __half out[8];
#pragma unroll
        for (int k = 0; k < 8; k++) {
            float r;
            if (RELU) r = fmaxf(fmaf(acc[k], d, __ldg(&bias[sub * 8 + k])), 0.f);
            else      r = acc[k] * d;
            out[k] = __float2half_rn(r);
        }
        reinterpret_cast<uint4*>(db)[node * U4R + sub] = *reinterpret_cast<uint4*>(out);
    }
}

// ------------------------------- Dense GEMM --------------------------------
// 2 rows per thread. Block 0 writes the zero sentinel row n at the OUTPUT
// stride, so a following agg reading O sees zeros at index n.

template <int FINP, int FINW, int FOUT, int EPI, int SRC>
__global__ void k_gemm_h(const float* __restrict__ W, const float* __restrict__ bias, int n) {
    __shared__ float Wsh[FINP * FOUT];
    for (int i = threadIdx.x; i < FINP * FOUT; i += blockDim.x)
        Wsh[i] = (i < FINW * FOUT) ? W[i] : 0.f;
    __syncthreads();

    const __half* X = SRC ? g_hB : g_hA;
    __half*       O = SRC ? g_hA : g_hB;

    if (blockIdx.x == 0 && threadIdx.x < FOUT / 8) {   // zero sentinel row n
        reinterpret_cast<uint4*>(O)[(long)n * (FOUT / 8) + threadIdx.x] =
            make_uint4(0u, 0u, 0u, 0u);
    }

    constexpr int TPR  = FOUT / 4;
    constexpr int RPB  = 256 / TPR;
    constexpr int RPB2 = RPB * 2;
    int slot = (int)(threadIdx.x / TPR);
    int row0 = blockIdx.x * RPB2 + slot;
    int row1 = row0 + RPB;
    int fx = (threadIdx.x % TPR) * 4;
    bool v0 = row0 < n, v1 = row1 < n;
    if (!v0) return;

    const uint4* xr0 = reinterpret_cast<const uint4*>(X + (long)row0 * FINP);
    const uint4* xr1 = reinterpret_cast<const uint4*>(X + (long)(v1 ? row1 : row0) * FINP);
    float4 a0 = make_float4(0.f, 0.f, 0.f, 0.f);
    float4 a1 = make_float4(0.f, 0.f, 0.f, 0.f);
#pragma unroll
    for (int q = 0; q < FINP / 8; q++) {
        uint4 p0 = __ldg(&xr0[q]);
        uint4 p1 = __ldg(&xr1[q]);
        const unsigned* u0 = &p0.x;
        const unsigned* u1 = &p1.x;
#pragma unroll
        for (int t = 0; t < 4; t++) {
            float2 f0 = __half22float2(*reinterpret_cast<const __half2*>(&u0[t]));
            float2 f1 = __half22float2(*reinterpret_cast<const __half2*>(&u1[t]));
            int k = q * 8 + t * 2;
            float4 w0 = *reinterpret_cast<const float4*>(&Wsh[k * FOUT + fx]);
            float4 w1 = *reinterpret_cast<const float4*>(&Wsh[(k + 1) * FOUT + fx]);
            a0.x = fmaf(f0.x, w0.x, fmaf(f0.y, w1.x, a0.x));
            a0.y = fmaf(f0.x, w0.y, fmaf(f0.y, w1.y, a0.y));
            a0.z = fmaf(f0.x, w0.z, fmaf(f0.y, w1.z, a0.z));
            a0.w = fmaf(f0.x, w0.w, fmaf(f0.y, w1.w, a0.w));
            a1.x = fmaf(f1.x, w0.x, fmaf(f1.y, w1.x, a1.x));
            a1.y = fmaf(f1.x, w0.y, fmaf(f1.y, w1.y, a1.y));
            a1.z = fmaf(f1.x, w0.z, fmaf(f1.y, w1.z, a1.z));
            a1.w = fmaf(f1.x, w0.w, fmaf(f1.y, w1.w, a1.w));
        }
    }

    float bx = 0.f, by = 0.f, bz = 0.f, bw = 0.f;
    if (EPI == 1) {
        bx = __ldg(&bias[fx + 0]); by = __ldg(&bias[fx + 1]);
        bz = __ldg(&bias[fx + 2]); bw = __ldg(&bias[fx + 3]);
    }
    {
        float4 acc = a0;
        if (EPI == 0) {
            float d = g_dinv[row0];
            acc.x *= d; acc.y *= d; acc.z *= d; acc.w *= d;
        } else {
            acc.x = fmaxf(acc.x + bx, 0.f); acc.y = fmaxf(acc.y + by, 0.f);
            acc.z = fmaxf(acc.z + bz, 0.f); acc.w = fmaxf(acc.w + bw, 0.f);
        }
        __half2* op = reinterpret_cast<__half2*>(&O[(long)row0 * FOUT + fx]);
        op[0] = __floats2half2_rn(acc.x, acc.y);
        op[1] = __floats2half2_rn(acc.z, acc.w);
    }
    if (v1) {
        float4 acc = a1;
        if (EPI == 0) {
            float d = g_dinv[row1];
            acc.x *= d; acc.y *= d; acc.z *= d; acc.w *= d;
        } else {
            acc.x = fmaxf(acc.x + bx, 0.f); acc.y = fmaxf(acc.y + by, 0.f);
            acc.z = fmaxf(acc.z + bz, 0.f); acc.w = fmaxf(acc.w + bw, 0.f);
        }
        __half2* op = reinterpret_cast<__half2*>(&O[(long)row1 * FOUT + fx]);
        op[0] = __floats2half2_rn(acc.x, acc.y);
        op[1] = __floats2half2_rn(acc.z, acc.w);
    }
}

// ------------------------- Pool + MLP head (fused) --------------------------
// Final features fp16 in g_hA (stride 32). batch sorted -> binary search.

__global__ void k_pool_mlp(const int* __restrict__ batch, int n,
                           const float* __restrict__ Wh1, const float* __restrict__ bh1,
                           const float* __restrict__ Wh2, const float* __restrict__ bh2,
                           float* __restrict__ out) {
    int g = blockIdx.x;
    int lo = 0, hi = n;
    while (lo < hi) { int mid = (lo + hi) >> 1; if (batch[mid] < g) lo = mid + 1; else hi = mid; }
    int start = lo;
    hi = n;
    while (lo < hi) { int mid = (lo + hi) >> 1; if (batch[mid] < g + 1) lo = mid + 1; else hi = mid; }
    int end = lo;

    __shared__ float partial[4][32];
    __shared__ float gsum[32];
    int f = threadIdx.x & 31;
    int r = threadIdx.x >> 5;
    float acc = 0.f;
    for (int i = start + r; i < end; i += 4) acc += __half2float(g_hA[(long)i * 32 + f]);
    partial[r][f] = acc;
    __syncthreads();

    if (threadIdx.x < 32) {
        float s = partial[0][f] + partial[1][f] + partial[2][f] + partial[3][f];
        float cnt = (float)((end - start) > 0 ? (end - start) : 1);
        gsum[f] = s / cnt;
    }
    __syncthreads();

    if (threadIdx.x < 32) {
        int o = threadIdx.x;
        float h = bh1[o];
#pragma unroll
        for (int k = 0; k < 32; k++) h = fmaf(gsum[k], Wh1[k * 32 + o], h);
        h = fmaxf(h, 0.f);
        float y = h * Wh2[o];
#pragma unroll
        for (int off = 16; off; off >>= 1) y += __shfl_down_sync(0xffffffffu, y, off);
        if (o == 0) out[g] = y + bh2[0];
    }
}

// ------------------------------- Launcher ----------------------------------

extern "C" void kernel_launch(void* const* d_in, const int* in_sizes, int n_in,
                              void* d_out, int out_size) {
    const float* x     = (const float*)d_in[0];
    const int*   ei    = (const int*)d_in[1];
    const int*   batch = (const int*)d_in[2];
    const float* W1  = (const float*)d_in[3];
    const float* b1  = (const float*)d_in[4];
    const float* W2  = (const float*)d_in[5];
    const float* b2  = (const float*)d_in[6];
    const float* W3  = (const float*)d_in[7];
    const float* b3  = (const float*)d_in[8];
    const float* Wh1 = (const float*)d_in[9];
    const float* bh1 = (const float*)d_in[10];
    const float* Wh2 = (const float*)d_in[11];
    const float* bh2 = (const float*)d_in[12];
    float* out = (float*)d_out;

    int N = in_sizes[0] / 25;
    int E = in_sizes[1] / 2;
    const int* src = ei;
    const int* dst = ei + E;

    int nThreads = 256;
    int nBlkN = (N + nThreads - 1) / nThreads;
    int nBlkE8 = (E + nThreads * 8 - 1) / (nThreads * 8);
    int agg32Blocks = (N + 63) / 64;   // 8 nodes/warp, 8 warps/block
    int agg64Blocks = (N + 31) / 32;   // 4 nodes/warp, 8 warps/block

    // --- Clear counters ---
    void* p = nullptr;
    cudaGetSymbolAddress(&p, g_cnt);
    cudaMemsetAsync(p, 0, N * sizeof(int));

    // --- Bucket adjacency build (single edge pass) ---
    k_fill<<<nBlkE8, nThreads>>>(src, dst, E);
    k_dinv_pad<<<nBlkN, nThreads>>>(N);

    // --- Layer 1: prep -> aggregate (stride 32) -> 25->64 GEMM ---
    k_prep<<<((N + 1) * 16 + 255) / 256, 256>>>(x, N);        // x -> A (+sentinel)
    k_agg_g<32, 0, 0><<<agg32Blocks, 256>>>(nullptr, N);      // A -> B
    k_gemm_h<32, 25, 64, 1, 1><<<(N + 31) / 32, 256>>>(W1, b1, N);  // B -> A

    // --- Layer 2 ---
    k_gemm_h<64, 64, 64, 0, 0><<<(N + 31) / 32, 256>>>(W2, nullptr, N);  // A -> B (+sentinel@64)
    k_agg_g<64, 1, 1><<<agg64Blocks, 256>>>(b2, N);                      // B -> A

    // --- Layer 3 ---
    k_gemm_h<64, 64, 32, 0, 0><<<(N + 63) / 64, 256>>>(W3, nullptr, N);  // A -> B (+sentinel@32)
    k_agg_g<32, 1, 1><<<agg32Blocks, 256>>>(b3, N);                      // B -> A

    // --- Pool + MLP head ---
    k_pool_mlp<<<GMAX, 128>>>(batch, N, Wh1, bh1, Wh2, bh2, out);
}

// round 12
// speedup vs baseline: 1.1840x; 1.0277x over previous
#include <cuda_runtime.h>
#include <cuda_fp16.h>

// ---------------------------------------------------------------------------
// MutationAwareGNN R12: unified agg shape — every aggregation uses 4-lane
// groups (8 virtual rows/warp); F=64 split into 2 half-row segments. 4-edge
// unrolled guard-free loop (buckets padded to mult 4, int4 col prefetch,
// 32 gathers in flight per warp). fp16 storage / fp32 accumulate, bucket
// adjacency, zero-row sentinels written by each producer at its stride.
// ---------------------------------------------------------------------------

#define NMAX 100000
#define EMAX 3200000
#define GMAX 256
#define CAP  128          // bucket capacity (Poisson(32) degrees: safe)

__device__ int    g_cnt[NMAX];
__device__ int    g_cnte4[NMAX];             // padded count, multiple of 4
__device__ int    g_col[(NMAX + 1) * CAP];   // +1 spare bucket absorbs over-reads
__device__ float  g_dinv[NMAX];
__device__ __half g_hA[(NMAX + 1) * 64];     // row n = zero sentinel (per layout)
__device__ __half g_hB[(NMAX + 1) * 64];

// ---------------------------- Bucket fill ----------------------------------

__global__ void k_fill(const int* __restrict__ src, const int* __restrict__ dst, int E) {
    int e8 = (blockIdx.x * blockDim.x + threadIdx.x) * 8;
    if (e8 + 7 < E) {
        int4 s0 = *reinterpret_cast<const int4*>(&src[e8]);
        int4 s1 = *reinterpret_cast<const int4*>(&src[e8 + 4]);
        int4 d0 = *reinterpret_cast<const int4*>(&dst[e8]);
        int4 d1 = *reinterpret_cast<const int4*>(&dst[e8 + 4]);
        int p0 = atomicAdd(&g_cnt[d0.x], 1);
        int p1 = atomicAdd(&g_cnt[d0.y], 1);
        int p2 = atomicAdd(&g_cnt[d0.z], 1);
        int p3 = atomicAdd(&g_cnt[d0.w], 1);
        int p4 = atomicAdd(&g_cnt[d1.x], 1);
        int p5 = atomicAdd(&g_cnt[d1.y], 1);
        int p6 = atomicAdd(&g_cnt[d1.z], 1);
        int p7 = atomicAdd(&g_cnt[d1.w], 1);
        if (p0 < CAP) g_col[d0.x * CAP + p0] = s0.x;
        if (p1 < CAP) g_col[d0.y * CAP + p1] = s0.y;
        if (p2 < CAP) g_col[d0.z * CAP + p2] = s0.z;
        if (p3 < CAP) g_col[d0.w * CAP + p3] = s0.w;
        if (p4 < CAP) g_col[d1.x * CAP + p4] = s1.x;
        if (p5 < CAP) g_col[d1.y * CAP + p5] = s1.y;
        if (p6 < CAP) g_col[d1.z * CAP + p6] = s1.z;
        if (p7 < CAP) g_col[d1.w * CAP + p7] = s1.w;
    } else {
        for (int e = e8; e < E; e++) {
            int d = dst[e];
            int p = atomicAdd(&g_cnt[d], 1);
            if (p < CAP) g_col[d * CAP + p] = src[e];
        }
    }
}

// dinv + pad buckets to multiple of 4 with sentinel index n (zero row).
__global__ void k_dinv_pad(int n) {
    int i = blockIdx.x * blockDim.x + threadIdx.x;
    if (i >= n) return;
    int c   = min(g_cnt[i], CAP);
    int ce4 = (c + 3) & ~3;
    for (int s = c; s < ce4; s++) g_col[i * CAP + s] = n;  // sentinel -> zero row
    g_cnte4[i] = ce4;
    g_dinv[i]  = rsqrtf((float)(c + 1));                   // +1 self-loop
}

// ------------------------------ Prep (layer 1) ------------------------------
// g_hA rows 0..n-1 = dinv_j * x_j (25 features padded to 32 fp16); row n = 0.

__global__ void k_prep(const float* __restrict__ x, int n) {
    int i = blockIdx.x * blockDim.x + threadIdx.x;   // half2 slot
    if (i >= (n + 1) * 16) return;
    int node = i >> 4, f2 = i & 15;
    float a = 0.f, b = 0.f;
    if (node < n) {
        float d = g_dinv[node];
        int f = f2 * 2;
        a = (f     < 25) ? d * __ldg(&x[node * 25 + f])     : 0.f;
        b = (f + 1 < 25) ? d * __ldg(&x[node * 25 + f + 1]) : 0.f;
    }
    reinterpret_cast<__half2*>(g_hA)[i] = __floats2half2_rn(a, b);
}

// ----------------------------- Aggregation ---------------------------------
// Unified shape: 4-lane groups, 8 virtual rows per warp. A virtual row is
// (node, seg) with seg in [0, SEGS); SEGS = F/32. 4-edge unrolled guard-free
// loop: buckets padded to multiple of 4, sentinel row n is zero, col indices
// prefetched as one int4 (bucket base 128-aligned, step 4).

template <int SEGS, int RELU, int SRC>
__global__ void k_agg_g(const float* __restrict__ bias, int n) {
    constexpr int ST = SEGS * 4;      // uint4 per full row (F/8)
    int wid  = (blockIdx.x * blockDim.x + threadIdx.x) >> 5;
    int lane = threadIdx.x & 31;
    int grp = lane >> 2;              // 0..7 virtual rows per warp
    int sub = lane & 3;               // uint4 chunk within segment
    int vrow = wid * 8 + grp;
    int node = (SEGS == 1) ? vrow : (vrow >> 1);
    int seg  = (SEGS == 1) ? 0    : (vrow & 1);
    bool valid = node < n;
    int nd = valid ? node : n;        // sentinel row safe to gather
    int so = seg * 4 + sub;           // uint4 offset within row

    const uint4* base = reinterpret_cast<const uint4*>(SRC ? g_hB : g_hA);
    __half*      db   = SRC ? g_hA : g_hB;

    // self-loop term
    float acc[8];
    {
        uint4 v = base[nd * ST + so];
        float2 f0 = __half22float2(*reinterpret_cast<__half2*>(&v.x));
        float2 f1 = __half22float2(*reinterpret_cast<__half2*>(&v.y));
        float2 f2 = __half22float2(*reinterpret_cast<__half2*>(&v.z));
        float2 f3 = __half22float2(*reinterpret_cast<__half2*>(&v.w));
        acc[0] = f0.x; acc[1] = f0.y; acc[2] = f1.x; acc[3] = f1.y;
        acc[4] = f2.x; acc[5] = f2.y; acc[6] = f3.x; acc[7] = f3.y;
    }

    int e    = node * CAP;
    int endv = e + (valid ? g_cnte4[node] : 0);
    int4 jj = *reinterpret_cast<const int4*>(&g_col[e]);
    while (e < endv) {
        uint4 v0 = base[jj.x * ST + so];
        uint4 v1 = base[jj.y * ST + so];
        uint4 v2 = base[jj.z * ST + so];
        uint4 v3 = base[jj.w * ST + so];
        e += 4;
        jj = *reinterpret_cast<const int4*>(&g_col[e]);   // prefetch (spare bucket)
        // pairwise fp16 pre-add (depth 1), then fp32 accumulate
        __half2 a0 = __hadd2(*reinterpret_cast<__half2*>(&v0.x), *reinterpret_cast<__half2*>(&v1.x));
        __half2 a1 = __hadd2(*reinterpret_cast<__half2*>(&v0.y), *reinterpret_cast<__half2*>(&v1.y));
        __half2 a2 = __hadd2(*reinterpret_cast<__half2*>(&v0.z), *reinterpret_cast<__half2*>(&v1.z));
        __half2 a3 = __hadd2(*reinterpret_cast<__half2*>(&v0.w), *reinterpret_cast<__half2*>(&v1.w));
        __half2 b0 = __hadd2(*reinterpret_cast<__half2*>(&v2.x), *reinterpret_cast<__half2*>(&v3.x));
        __half2 b1 = __hadd2(*reinterpret_cast<__half2*>(&v2.y), *reinterpret_cast<__half2*>(&v3.y));
        __half2 b2 = __hadd2(*reinterpret_cast<__half2*>(&v2.z), *reinterpret_cast<__half2*>(&v3.z));
        __half2 b3 = __hadd2(*reinterpret_cast<__half2*>(&v2.w), *reinterpret_cast<__half2*>(&v3.w));
        float2 fa0 = __half22float2(a0), fa1 = __half22float2(a1);
        float2 fa2 = __half22float2(a2), fa3 = __half22float2(a3);
        float2 fb0 = __half22float2(b0), fb1 = __half22float2(b1);
        float2 fb2 = __half22float2(b2), fb3 = __half22float2(b3);
        acc[0] += fa0.x + fb0.x; acc[1] += fa0.y + fb0.y;
        acc[2] += fa1.x + fb1.x; acc[3] += fa1.y + fb1.y;
        acc[4] += fa2.x + fb2.x; acc[5] += fa2.y + fb2.y;
        acc[6] += fa3.x + fb3.x; acc[7] += fa3.y + fb3.y;
    }

    if (valid) {
        float d = g_dinv[node];
        __half out[8];
#pragma unroll
        for (int k = 0; k < 8; k++) {
            float r;
            if (RELU) r = fmaxf(fmaf(acc[k], d, __ldg(&bias[seg * 32 + sub * 8 + k])), 0.f);
            else      r = acc[k] * d;
            out[k] = __float2half_rn(r);
        }
        reinterpret_cast<uint4*>(db)[node * ST + so] = *reinterpret_cast<uint4*>(out);
    }
}

// ------------------------------- Dense GEMM --------------------------------
// 2 rows per thread. Block 0 writes the zero sentinel row n at the OUTPUT
// stride, so a following agg reading O sees zeros at index n.

template <int FINP, int FINW, int FOUT, int EPI, int SRC>
__global__ void k_gemm_h(const float* __restrict__ W, const float* __restrict__ bias, int n) {
    __shared__ float Wsh[FINP * FOUT];
    for (int i = threadIdx.x; i < FINP * FOUT; i += blockDim.x)
        Wsh[i] = (i < FINW * FOUT) ? W[i] : 0.f;
    __syncthreads();

    const __half* X = SRC ? g_hB : g_hA;
    __half*       O = SRC ? g_hA : g_hB;

    if (blockIdx.x == 0 && threadIdx.x < FOUT / 8) {   // zero sentinel row n
        reinterpret_cast<uint4*>(O)[(long)n * (FOUT / 8) + threadIdx.x] =
            make_uint4(0u, 0u, 0u, 0u);
    }

    constexpr int TPR  = FOUT / 4;
    constexpr int RPB  = 256 / TPR;
    constexpr int RPB2 = RPB * 2;
    int slot = (int)(threadIdx.x / TPR);
    int row0 = blockIdx.x * RPB2 + slot;
    int row1 = row0 + RPB;
    int fx = (threadIdx.x % TPR) * 4;
    bool v0 = row0 < n, v1 = row1 < n;
    if (!v0) return;

    const uint4* xr0 = reinterpret_cast<const uint4*>(X + (long)row0 * FINP);
    const uint4* xr1 = reinterpret_cast<const uint4*>(X + (long)(v1 ? row1 : row0) * FINP);
    float4 a0 = make_float4(0.f, 0.f, 0.f, 0.f);
    float4 a1 = make_float4(0.f, 0.f, 0.f, 0.f);
#pragma unroll
    for (int q = 0; q < FINP / 8; q++) {
        uint4 p0 = __ldg(&xr0[q]);
        uint4 p1 = __ldg(&xr1[q]);
        const unsigned* u0 = &p0.x;
        const unsigned* u1 = &p1.x;
#pragma unroll
        for (int t = 0; t < 4; t++) {
            float2 f0 = __half22float2(*reinterpret_cast<const __half2*>(&u0[t]));
            float2 f1 = __half22float2(*reinterpret_cast<const __half2*>(&u1[t]));
            int k = q * 8 + t * 2;
            float4 w0 = *reinterpret_cast<const float4*>(&Wsh[k * FOUT + fx]);
            float4 w1 = *reinterpret_cast<const float4*>(&Wsh[(k + 1) * FOUT + fx]);
            a0.x = fmaf(f0.x, w0.x, fmaf(f0.y, w1.x, a0.x));
            a0.y = fmaf(f0.x, w0.y, fmaf(f0.y, w1.y, a0.y));
            a0.z = fmaf(f0.x, w0.z, fmaf(f0.y, w1.z, a0.z));
            a0.w = fmaf(f0.x, w0.w, fmaf(f0.y, w1.w, a0.w));
            a1.x = fmaf(f1.x, w0.x, fmaf(f1.y, w1.x, a1.x));
            a1.y = fmaf(f1.x, w0.y, fmaf(f1.y, w1.y, a1.y));
            a1.z = fmaf(f1.x, w0.z, fmaf(f1.y, w1.z, a1.z));
            a1.w = fmaf(f1.x, w0.w, fmaf(f1.y, w1.w, a1.w));
        }
    }

    float bx = 0.f, by = 0.f, bz = 0.f, bw = 0.f;
    if (EPI == 1) {
        bx = __ldg(&bias[fx + 0]); by = __ldg(&bias[fx + 1]);
        bz = __ldg(&bias[fx + 2]); bw = __ldg(&bias[fx + 3]);
    }
    {
        float4 acc = a0;
        if (EPI == 0) {
            float d = g_dinv[row0];
            acc.x *= d; acc.y *= d; acc.z *= d; acc.w *= d;
        } else {
            acc.x = fmaxf(acc.x + bx, 0.f); acc.y = fmaxf(acc.y + by, 0.f);
            acc.z = fmaxf(acc.z + bz, 0.f); acc.w = fmaxf(acc.w + bw, 0.f);
        }
        __half2* op = reinterpret_cast<__half2*>(&O[(long)row0 * FOUT + fx]);
        op[0] = __floats2half2_rn(acc.x, acc.y);
        op[1] = __floats2half2_rn(acc.z, acc.w);
    }
    if (v1) {
        float4 acc = a1;
        if (EPI == 0) {
            float d = g_dinv[row1];
            acc.x *= d; acc.y *= d; acc.z *= d; acc.w *= d;
        } else {
            acc.x = fmaxf(acc.x + bx, 0.f); acc.y = fmaxf(acc.y + by, 0.f);
            acc.z = fmaxf(acc.z + bz, 0.f); acc.w = fmaxf(acc.w + bw, 0.f);
        }
        __half2* op = reinterpret_cast<__half2*>(&O[(long)row1 * FOUT + fx]);
        op[0] = __floats2half2_rn(acc.x, acc.y);
        op[1] = __floats2half2_rn(acc.z, acc.w);
    }
}

// ------------------------- Pool + MLP head (fused) --------------------------
// Final features fp16 in g_hA (stride 32). batch sorted -> binary search.

__global__ void k_pool_mlp(const int* __restrict__ batch, int n,
                           const float* __restrict__ Wh1, const float* __restrict__ bh1,
                           const float* __restrict__ Wh2, const float* __restrict__ bh2,
                           float* __restrict__ out) {
    int g = blockIdx.x;
    int lo = 0, hi = n;
    while (lo < hi) { int mid = (lo + hi) >> 1; if (batch[mid] < g) lo = mid + 1; else hi = mid; }
    int start = lo;
    hi = n;
    while (lo < hi) { int mid = (lo + hi) >> 1; if (batch[mid] < g + 1) lo = mid + 1; else hi = mid; }
    int end = lo;

    __shared__ float partial[4][32];
    __shared__ float gsum[32];
    int f = threadIdx.x & 31;
    int r = threadIdx.x >> 5;
    float acc = 0.f;
    for (int i = start + r; i < end; i += 4) acc += __half2float(g_hA[(long)i * 32 + f]);
    partial[r][f] = acc;
    __syncthreads();

    if (threadIdx.x < 32) {
        float s = partial[0][f] + partial[1][f] + partial[2][f] + partial[3][f];
        float cnt = (float)((end - start) > 0 ? (end - start) : 1);
        gsum[f] = s / cnt;
    }
    __syncthreads();

    if (threadIdx.x < 32) {
        int o = threadIdx.x;
        float h = bh1[o];
#pragma unroll
        for (int k = 0; k < 32; k++) h = fmaf(gsum[k], Wh1[k * 32 + o], h);
        h = fmaxf(h, 0.f);
        float y = h * Wh2[o];
#pragma unroll
        for (int off = 16; off; off >>= 1) y += __shfl_down_sync(0xffffffffu, y, off);
        if (o == 0) out[g] = y + bh2[0];
    }
}

// ------------------------------- Launcher ----------------------------------

extern "C" void kernel_launch(void* const* d_in, const int* in_sizes, int n_in,
                              void* d_out, int out_size) {
    const float* x     = (const float*)d_in[0];
    const int*   ei    = (const int*)d_in[1];
    const int*   batch = (const int*)d_in[2];
    const float* W1  = (const float*)d_in[3];
    const float* b1  = (const float*)d_in[4];
    const float* W2  = (const float*)d_in[5];
    const float* b2  = (const float*)d_in[6];
    const float* W3  = (const float*)d_in[7];
    const float* b3  = (const float*)d_in[8];
    const float* Wh1 = (const float*)d_in[9];
    const float* bh1 = (const float*)d_in[10];
    const float* Wh2 = (const float*)d_in[11];
    const float* bh2 = (const float*)d_in[12];
    float* out = (float*)d_out;

    int N = in_sizes[0] / 25;
    int E = in_sizes[1] / 2;
    const int* src = ei;
    const int* dst = ei + E;

    int nThreads = 256;
    int nBlkN = (N + nThreads - 1) / nThreads;
    int nBlkE8 = (E + nThreads * 8 - 1) / (nThreads * 8);
    int agg1Blocks = (N + 63) / 64;          // 8 vrows/warp, SEGS=1
    int agg2Blocks = (2 * N + 63) / 64;      // SEGS=2 -> 2N virtual rows

    // --- Clear counters ---
    void* p = nullptr;
    cudaGetSymbolAddress(&p, g_cnt);
    cudaMemsetAsync(p, 0, N * sizeof(int));

    // --- Bucket adjacency build (single edge pass) ---
    k_fill<<<nBlkE8, nThreads>>>(src, dst, E);
    k_dinv_pad<<<nBlkN, nThreads>>>(N);

    // --- Layer 1: prep -> aggregate (stride 32) -> 25->64 GEMM ---
    k_prep<<<((N + 1) * 16 + 255) / 256, 256>>>(x, N);        // x -> A (+sentinel)
    k_agg_g<1, 0, 0><<<agg1Blocks, 256>>>(nullptr, N);        // A -> B
    k_gemm_h<32, 25, 64, 1, 1><<<(N + 31) / 32, 256>>>(W1, b1, N);  // B -> A

    // --- Layer 2 ---
    k_gemm_h<64, 64, 64, 0, 0><<<(N + 31) / 32, 256>>>(W2, nullptr, N);  // A -> B (+sentinel@64)
    k_agg_g<2, 1, 1><<<agg2Blocks, 256>>>(b2, N);                        // B -> A

    // --- Layer 3 ---
    k_gemm_h<64, 64, 32, 0, 0><<<(N + 63) / 64, 256>>>(W3, nullptr, N);  // A -> B (+sentinel@32)
    k_agg_g<1, 1, 1><<<agg1Blocks, 256>>>(b3, N);                        // B -> A

    // --- Pool + MLP head ---
    k_pool_mlp<<<GMAX, 128>>>(batch, N, Wh1, bh1, Wh2, bh2, out);
}